// round 14
// baseline (speedup 1.0000x reference)
#include <cuda_runtime.h>
#include <cuda_bf16.h>

// SemiLoss focal loss (gamma=6), single fused kernel, smem-staged variant.
//
// Insight: with random classes, the scattered gather already touches ~10.5 of
// 11 class lines per 128B run -> DRAM traffic == read-everything (~46MB). So
// read everything COALESCED (float4 streaming, MLP=11 independent loads into
// smem) and do the per-pixel class select as ONE conflict-free smem LDS
// instead of a scattered global gather (11 lines/LDG) or K-way FSEL (ALU-bound).
//
//   logits : [N, K, P] f32       (staging path requires K == 11)
//   seg    : [N, P]    int64 or int32 (runtime-sniffed)
//   label  : [N]       same int dtype
//   loss = -sum_{n: label[n]!=0} sum_p (1-exp(lp))^6 * lp / count(label!=0)
//   out  = [loss, 0, loss, 0, ...]
//
// Completion: atomicAdd(g_total) + threadfence + atomicInc(g_done) wrapping
// at gridDim.x (self-resetting); last block finalizes out and resets g_total
// so the kernel is deterministic across CUDA-graph replays.

#define THREADS   256
#define CHUNK_PX  1024                 // 256 thr * 4 px
#define KFIX      11
#define MAXROWS   256

__device__ double       g_total = 0.0;
__device__ unsigned int g_done  = 0u;

__device__ __forceinline__ float focal_term(float lp)
{
    float pt = __expf(lp);
    float u  = 1.0f - pt;
    float u2 = u * u;
    return u2 * u2 * u2 * lp;   // positive form; negated at the end
}

// ---- shared prologue: dtype sniff + active-row ballot map ----------------
// Returns cnt; fills s_rowOf. Call with all threads.
__device__ __forceinline__ int build_row_map(
    const void* seg, const void* label, int N, int tid,
    int* s_is64, unsigned* s_masks, short* s_rowOf, int* is64_out)
{
    const int nwords = (N + 31) >> 5;

    if (tid < 32) {
        const int* w = (const int*)seg;   // int64 LE => odd words are 0
        unsigned b = __ballot_sync(0xffffffffu, w[2 * tid + 1] == 0);
        if (tid == 0) *s_is64 = (b == 0xffffffffu) ? 1 : 0;
    }
    __syncthreads();
    const int is64 = *s_is64;
    *is64_out = is64;

    {
        bool a = false;
        if (tid < N) {
            long long lv;
            if (is64) lv = ((const long long*)label)[tid];
            else      lv = (long long)((const int*)label)[tid];
            a = (lv != 0);
        }
        unsigned b = __ballot_sync(0xffffffffu, a);
        if ((tid & 31) == 0 && (tid >> 5) < nwords)
            s_masks[tid >> 5] = b;
    }
    __syncthreads();

    int cnt = 0;
    #pragma unroll 4
    for (int j = 0; j < nwords; ++j) cnt += __popc(s_masks[j]);

    if (tid < N) {
        int w = tid >> 5, l = tid & 31;
        if ((s_masks[w] >> l) & 1u) {
            int pre = __popc(s_masks[w] & ((1u << l) - 1u));
            for (int j = 0; j < w; ++j) pre += __popc(s_masks[j]);
            s_rowOf[pre] = (short)tid;
        }
    }
    __syncthreads();
    return cnt;
}

// ---- shared epilogue: block reduce + completion + finalize ---------------
__device__ __forceinline__ void finish(
    float acc, int tid, int cnt, double* s_part,
    float* out, int out_size)
{
    for (int off = 16; off > 0; off >>= 1)
        acc += __shfl_down_sync(0xffffffffu, acc, off);
    const int lane = tid & 31, wid = tid >> 5;
    if (lane == 0) s_part[wid] = (double)acc;
    __syncthreads();

    __shared__ int s_islast;
    if (tid == 0) {
        double v = 0.0;
        #pragma unroll
        for (int w = 0; w < 8; ++w) v += s_part[w];
        if (v != 0.0) atomicAdd(&g_total, v);
        __threadfence();
        unsigned old = atomicInc(&g_done, gridDim.x - 1u);
        s_islast = (old == gridDim.x - 1u) ? 1 : 0;
    }
    __syncthreads();

    if (s_islast) {
        __shared__ float s_loss;
        if (tid == 0) {
            double tot = *((volatile double*)&g_total);
            double cd  = (cnt > 0) ? (double)cnt : 1.0;
            s_loss = (float)(-tot / cd);
            g_total = 0.0;          // reset for next graph replay
            __threadfence();
        }
        __syncthreads();
        float loss = s_loss;
        for (int i = tid; i < out_size; i += blockDim.x)
            out[i] = (i == 0 || i == 2) ? loss : 0.0f;
    }
}

// ===== staged kernel (K == 11) ============================================
__global__ __launch_bounds__(THREADS, 5)
void semiloss_staged(const float* __restrict__ logits,
                     const void*  __restrict__ seg,
                     const void*  __restrict__ label,
                     int N, int P, int chunksPerRow,
                     float* __restrict__ out, int out_size)
{
    __shared__ float    s_planes[KFIX * CHUNK_PX];   // 44 KB
    __shared__ int      s_is64;
    __shared__ unsigned s_masks[MAXROWS / 32];
    __shared__ short    s_rowOf[MAXROWS];
    __shared__ double   s_part[8];

    const int tid = threadIdx.x;
    int is64;
    const int cnt = build_row_map(seg, label, N, tid,
                                  &s_is64, s_masks, s_rowOf, &is64);

    float acc = 0.0f;
    const int q = blockIdx.x / chunksPerRow;          // active-row ordinal
    if (q < cnt) {
        const int chunk = blockIdx.x - q * chunksPerRow;
        const int row   = s_rowOf[q];
        const int pc    = chunk * CHUNK_PX;           // chunk base pixel
        const float* base = logits + (size_t)row * (size_t)KFIX * (size_t)P;

        if (pc + CHUNK_PX <= P) {
            // ---- stage all 11 plane slices, coalesced float4, MLP=11 ----
            #pragma unroll
            for (int k = 0; k < KFIX; ++k) {
                float4 v = __ldg((const float4*)(base + (size_t)k * P + pc + 4 * tid));
                *(float4*)&s_planes[k * CHUNK_PX + 4 * tid] = v;
            }
            // ---- seg classes, stride-256 scalar (independent) ----
            int c[4];
            if (is64) {
                const long long* s = (const long long*)seg + (size_t)row * P + pc;
                #pragma unroll
                for (int i = 0; i < 4; ++i)
                    c[i] = (int)__ldg(s + tid + 256 * i);
            } else {
                const int* s = (const int*)seg + (size_t)row * P + pc;
                #pragma unroll
                for (int i = 0; i < 4; ++i)
                    c[i] = __ldg(s + tid + 256 * i);
            }
            __syncthreads();
            // ---- conflict-free smem gather: addr%32 == lane ----
            #pragma unroll
            for (int i = 0; i < 4; ++i) {
                float lp = s_planes[c[i] * CHUNK_PX + tid + 256 * i];
                acc += focal_term(lp);
            }
        } else {
            // tail chunk: direct scalar gather (uniform branch per block)
            int pEnd = pc + CHUNK_PX;
            if (pEnd > P) pEnd = P;
            for (int p = pc + tid; p < pEnd; p += THREADS) {
                int cc;
                if (is64) cc = (int)((const long long*)seg)[(size_t)row * P + p];
                else      cc = ((const int*)seg)[(size_t)row * P + p];
                acc += focal_term(__ldg(base + (size_t)cc * P + p));
            }
        }
    }

    finish(acc, tid, cnt, s_part, out, out_size);
}

// ===== generic gather fallback (any K) — R11 structure ====================
__global__ __launch_bounds__(THREADS)
void semiloss_gather(const float* __restrict__ logits,
                     const void*  __restrict__ seg,
                     const void*  __restrict__ label,
                     int N, int K, int P, int chunksPerRow,
                     float* __restrict__ out, int out_size)
{
    __shared__ int      s_is64;
    __shared__ unsigned s_masks[MAXROWS / 32];
    __shared__ short    s_rowOf[MAXROWS];
    __shared__ double   s_part[8];

    const int tid = threadIdx.x;
    int is64;
    const int cnt = build_row_map(seg, label, N, tid,
                                  &s_is64, s_masks, s_rowOf, &is64);

    float acc = 0.0f;
    const int q = blockIdx.x / chunksPerRow;
    if (q < cnt) {
        const int chunk = blockIdx.x - q * chunksPerRow;
        const int row   = s_rowOf[q];
        const int pc    = chunk * (THREADS * 8);
        const int p0    = pc + tid;
        const float* base = logits + (size_t)row * (size_t)K * (size_t)P;

        if (p0 + 7 * THREADS < P) {
            int c[8];
            if (is64) {
                const long long* s = (const long long*)seg + (size_t)row * P;
                #pragma unroll
                for (int i = 0; i < 8; ++i)
                    c[i] = (int)__ldg(s + p0 + THREADS * i);
            } else {
                const int* s = (const int*)seg + (size_t)row * P;
                #pragma unroll
                for (int i = 0; i < 8; ++i)
                    c[i] = __ldg(s + p0 + THREADS * i);
            }
            float l[8];
            #pragma unroll
            for (int i = 0; i < 8; ++i)
                l[i] = __ldg(base + (size_t)c[i] * P + p0 + THREADS * i);
            #pragma unroll
            for (int i = 0; i < 8; ++i)
                acc += focal_term(l[i]);
        } else {
            int pEnd = pc + THREADS * 8;
            if (pEnd > P) pEnd = P;
            for (int p = p0; p < pEnd; p += THREADS) {
                int cc;
                if (is64) cc = (int)((const long long*)seg)[(size_t)row * P + p];
                else      cc = ((const int*)seg)[(size_t)row * P + p];
                acc += focal_term(__ldg(base + (size_t)cc * P + p));
            }
        }
    }

    finish(acc, tid, cnt, s_part, out, out_size);
}

extern "C" void kernel_launch(void* const* d_in, const int* in_sizes, int n_in,
                              void* d_out, int out_size)
{
    const float* logits = (const float*)d_in[0];
    const void*  seg    = d_in[1];
    const void*  label  = d_in[2];

    int N = in_sizes[2];                 // B*S
    int P = in_sizes[1] / N;             // H*W
    int K = in_sizes[0] / in_sizes[1];   // classes

    if (K == KFIX) {
        int chunksPerRow = (P + CHUNK_PX - 1) / CHUNK_PX;
        unsigned int blocks = (unsigned int)N * (unsigned int)chunksPerRow;
        semiloss_staged<<<blocks, THREADS>>>(logits, seg, label,
                                             N, P, chunksPerRow,
                                             (float*)d_out, out_size);
    } else {
        int chunksPerRow = (P + THREADS * 8 - 1) / (THREADS * 8);
        unsigned int blocks = (unsigned int)N * (unsigned int)chunksPerRow;
        semiloss_gather<<<blocks, THREADS>>>(logits, seg, label,
                                             N, K, P, chunksPerRow,
                                             (float*)d_out, out_size);
    }
}

// round 15
// speedup vs baseline: 1.5657x; 1.5657x over previous
#include <cuda_runtime.h>
#include <cuda_bf16.h>

// SemiLoss focal loss (gamma=6), single fused kernel.
// R11 (measured best, 10.30us) with exactly one change: grid halved to
// ceil(N*chunksPerRow/2) with a <=2-iteration chunk loop. At cnt = N/2
// (the benchmark case) every launched block does exactly ONE 2048-px chunk
// with the identical 8-px/thread stride-256 gather schedule — zero idle
// blocks, half the prologue/atomic instances. Other cnt values covered by
// the loop.
//
//   logits : [N, K, P] f32
//   seg    : [N, P]    int64 or int32 (runtime-sniffed)
//   label  : [N]       same int dtype
//   loss = -sum_{n: label[n]!=0} sum_p (1-exp(lp))^6 * lp / count(label!=0)
//   out  = [loss, 0, loss, 0, ...]
//
// Completion: atomicAdd(g_total) + threadfence + atomicInc(g_done) wrapping
// at gridDim.x (self-resetting); last block finalizes out and resets g_total
// so the kernel is deterministic across CUDA-graph replays.

#define THREADS   256
#define PXPT      8                    // pixels per thread per chunk
#define CHUNK_PX  (THREADS * PXPT)     // 2048
#define MAXROWS   256                  // N <= 256 (ballot mapper)

__device__ double       g_total = 0.0;
__device__ unsigned int g_done  = 0u;

__device__ __forceinline__ float focal_term(float lp)
{
    float pt = __expf(lp);
    float u  = 1.0f - pt;
    float u2 = u * u;
    return u2 * u2 * u2 * lp;   // positive form; negated at the end
}

__global__ __launch_bounds__(THREADS)
void semiloss_fused(const float* __restrict__ logits,
                    const void*  __restrict__ seg,
                    const void*  __restrict__ label,
                    int N, int K, int P, int chunksPerRow,
                    float* __restrict__ out, int out_size)
{
    const int tid = threadIdx.x;

    // ---- prologue: dtype sniff + active-row ballot map ----
    __shared__ int      s_is64;
    __shared__ unsigned s_masks[MAXROWS / 32];
    __shared__ short    s_rowOf[MAXROWS];   // ordinal -> row
    const int nwords = (N + 31) >> 5;

    if (tid < 32) {
        // int64 (LE) => every odd 32-bit word of seg is 0
        const int* w = (const int*)seg;
        unsigned b = __ballot_sync(0xffffffffu, w[2 * tid + 1] == 0);
        if (tid == 0) s_is64 = (b == 0xffffffffu) ? 1 : 0;
    }
    __syncthreads();
    const int is64 = s_is64;

    {
        bool a = false;
        if (tid < N) {
            long long lv;
            if (is64) lv = ((const long long*)label)[tid];
            else      lv = (long long)((const int*)label)[tid];
            a = (lv != 0);
        }
        unsigned b = __ballot_sync(0xffffffffu, a);
        if ((tid & 31) == 0 && (tid >> 5) < nwords)
            s_masks[tid >> 5] = b;
    }
    __syncthreads();

    int cnt = 0;
    #pragma unroll 4
    for (int j = 0; j < nwords; ++j) cnt += __popc(s_masks[j]);

    if (tid < N) {
        int w = tid >> 5, l = tid & 31;
        if ((s_masks[w] >> l) & 1u) {
            int pre = __popc(s_masks[w] & ((1u << l) - 1u));
            for (int j = 0; j < w; ++j) pre += __popc(s_masks[j]);
            s_rowOf[pre] = (short)tid;
        }
    }
    __syncthreads();

    // ---- gather-reduce: <=2 chunks per block (exactly 1 at cnt = N/2) ----
    float acc = 0.0f;
    const int totalChunks = cnt * chunksPerRow;

    for (int u = blockIdx.x; u < totalChunks; u += gridDim.x) {
        const int q     = u / chunksPerRow;       // active-row ordinal
        const int chunk = u - q * chunksPerRow;
        const int row   = s_rowOf[q];
        const int p0    = chunk * CHUNK_PX + tid;
        const float* base = logits + (size_t)row * (size_t)K * (size_t)P;

        if (p0 + (PXPT - 1) * THREADS < P) {
            int c[PXPT];
            if (is64) {
                const long long* s = (const long long*)seg + (size_t)row * P;
                #pragma unroll
                for (int i = 0; i < PXPT; ++i)
                    c[i] = (int)__ldg(s + p0 + THREADS * i);
            } else {
                const int* s = (const int*)seg + (size_t)row * P;
                #pragma unroll
                for (int i = 0; i < PXPT; ++i)
                    c[i] = __ldg(s + p0 + THREADS * i);
            }
            float l[PXPT];
            #pragma unroll
            for (int i = 0; i < PXPT; ++i)
                l[i] = __ldg(base + (size_t)c[i] * P + p0 + THREADS * i);
            #pragma unroll
            for (int i = 0; i < PXPT; ++i)
                acc += focal_term(l[i]);
        } else {
            // tail chunk: scalar fallback over the chunk's valid pixels
            int pEnd = chunk * CHUNK_PX + CHUNK_PX;
            if (pEnd > P) pEnd = P;
            for (int p = p0; p < pEnd; p += THREADS) {
                int cc;
                if (is64) cc = (int)((const long long*)seg)[(size_t)row * P + p];
                else      cc = ((const int*)seg)[(size_t)row * P + p];
                acc += focal_term(__ldg(base + (size_t)cc * P + p));
            }
        }
    }

    // ---- block reduction (8 warps) ----
    for (int off = 16; off > 0; off >>= 1)
        acc += __shfl_down_sync(0xffffffffu, acc, off);
    __shared__ double s_part[8];
    const int lane = tid & 31, wid = tid >> 5;
    if (lane == 0) s_part[wid] = (double)acc;
    __syncthreads();

    __shared__ int s_islast;
    if (tid == 0) {
        double v = 0.0;
        #pragma unroll
        for (int w = 0; w < 8; ++w) v += s_part[w];
        if (v != 0.0) atomicAdd(&g_total, v);
        __threadfence();
        unsigned old = atomicInc(&g_done, gridDim.x - 1u);
        s_islast = (old == gridDim.x - 1u) ? 1 : 0;
    }
    __syncthreads();

    // ---- last block: finalize ----
    if (s_islast) {
        __shared__ float s_loss;
        if (tid == 0) {
            double tot = *((volatile double*)&g_total);
            double cd  = (cnt > 0) ? (double)cnt : 1.0;
            s_loss = (float)(-tot / cd);
            g_total = 0.0;          // reset for next graph replay
            __threadfence();
        }
        __syncthreads();
        float loss = s_loss;
        for (int i = tid; i < out_size; i += blockDim.x)
            out[i] = (i == 0 || i == 2) ? loss : 0.0f;
    }
}

extern "C" void kernel_launch(void* const* d_in, const int* in_sizes, int n_in,
                              void* d_out, int out_size)
{
    const float* logits = (const float*)d_in[0];
    const void*  seg    = d_in[1];
    const void*  label  = d_in[2];

    int N = in_sizes[2];                 // B*S
    int P = in_sizes[1] / N;             // H*W
    int K = in_sizes[0] / in_sizes[1];   // classes

    int chunksPerRow = (P + CHUNK_PX - 1) / CHUNK_PX;
    // Half the full-activity chunk count: at cnt = N/2 every block does
    // exactly one chunk; any cnt covered by the <=2-iteration loop.
    unsigned int blocks = ((unsigned int)N * (unsigned int)chunksPerRow + 1u) / 2u;
    if (blocks == 0) blocks = 1;

    semiloss_fused<<<blocks, THREADS>>>(logits, seg, label,
                                        N, K, P, chunksPerRow,
                                        (float*)d_out, out_size);
}

// round 16
// speedup vs baseline: 1.5754x; 1.0062x over previous
#include <cuda_runtime.h>
#include <cuda_bf16.h>

// SemiLoss focal loss (gamma=6), single fused kernel — FINAL (R11 config,
// measured best 10.30us; resubmitted verbatim to confirm reproducibility).
//
// Measured-best configuration after a 14-round sweep:
//   - 256-thread blocks, 2048-px chunks, grid = N*chunksPerRow (864)
//   - 8 px/thread, scalar stride-256 seg loads, 32-consecutive-px warp
//     gathers (deep per-thread MLP beat every balance-oriented variant)
//   - O(1) ballot prologue for the active-row map, __expf focal math
//
//   logits : [N, K, P] f32
//   seg    : [N, P]    int64 or int32 (runtime-sniffed)
//   label  : [N]       same int dtype
//   loss = -sum_{n: label[n]!=0} sum_p (1-exp(lp))^6 * lp / count(label!=0)
//   out  = [loss, 0, loss, 0, ...]
//
// Completion: atomicAdd(g_total) + threadfence + atomicInc(g_done) wrapping
// at gridDim.x (self-resetting); last block finalizes out and resets g_total
// so the kernel is deterministic across CUDA-graph replays.

#define THREADS   256
#define PXPT      8                    // pixels per thread
#define CHUNK_PX  (THREADS * PXPT)     // 2048
#define MAXROWS   256                  // N <= 256 (ballot mapper)

__device__ double       g_total = 0.0;
__device__ unsigned int g_done  = 0u;

__device__ __forceinline__ float focal_term(float lp)
{
    float pt = __expf(lp);
    float u  = 1.0f - pt;
    float u2 = u * u;
    return u2 * u2 * u2 * lp;   // positive form; negated at the end
}

__global__ __launch_bounds__(THREADS)
void semiloss_fused(const float* __restrict__ logits,
                    const void*  __restrict__ seg,
                    const void*  __restrict__ label,
                    int N, int K, int P, int chunksPerRow,
                    float* __restrict__ out, int out_size)
{
    const int tid = threadIdx.x;

    // ---- prologue: dtype sniff + active-row ballot map ----
    __shared__ int      s_is64;
    __shared__ unsigned s_masks[MAXROWS / 32];
    __shared__ short    s_rowOf[MAXROWS];   // ordinal -> row
    const int nwords = (N + 31) >> 5;

    if (tid < 32) {
        // int64 (LE) => every odd 32-bit word of seg is 0
        const int* w = (const int*)seg;
        unsigned b = __ballot_sync(0xffffffffu, w[2 * tid + 1] == 0);
        if (tid == 0) s_is64 = (b == 0xffffffffu) ? 1 : 0;
    }
    __syncthreads();
    const int is64 = s_is64;

    {
        bool a = false;
        if (tid < N) {
            long long lv;
            if (is64) lv = ((const long long*)label)[tid];
            else      lv = (long long)((const int*)label)[tid];
            a = (lv != 0);
        }
        unsigned b = __ballot_sync(0xffffffffu, a);
        if ((tid & 31) == 0 && (tid >> 5) < nwords)
            s_masks[tid >> 5] = b;
    }
    __syncthreads();

    int cnt = 0;
    #pragma unroll 4
    for (int j = 0; j < nwords; ++j) cnt += __popc(s_masks[j]);

    if (tid < N) {
        int w = tid >> 5, l = tid & 31;
        if ((s_masks[w] >> l) & 1u) {
            int pre = __popc(s_masks[w] & ((1u << l) - 1u));
            for (int j = 0; j < w; ++j) pre += __popc(s_masks[j]);
            s_rowOf[pre] = (short)tid;
        }
    }
    __syncthreads();

    // ---- gather-reduce over this block's chunk (if any) ----
    float acc = 0.0f;
    {
        const int q = blockIdx.x / chunksPerRow;     // active-row ordinal
        if (q < cnt) {
            const int chunk = blockIdx.x - q * chunksPerRow;
            const int row   = s_rowOf[q];
            const int p0    = chunk * CHUNK_PX + tid;
            const float* base = logits + (size_t)row * (size_t)K * (size_t)P;

            if (p0 + (PXPT - 1) * THREADS < P) {
                int c[PXPT];
                if (is64) {
                    const long long* s = (const long long*)seg + (size_t)row * P;
                    #pragma unroll
                    for (int i = 0; i < PXPT; ++i)
                        c[i] = (int)__ldg(s + p0 + THREADS * i);
                } else {
                    const int* s = (const int*)seg + (size_t)row * P;
                    #pragma unroll
                    for (int i = 0; i < PXPT; ++i)
                        c[i] = __ldg(s + p0 + THREADS * i);
                }
                float l[PXPT];
                #pragma unroll
                for (int i = 0; i < PXPT; ++i)
                    l[i] = __ldg(base + (size_t)c[i] * P + p0 + THREADS * i);
                #pragma unroll
                for (int i = 0; i < PXPT; ++i)
                    acc += focal_term(l[i]);
            } else {
                // tail chunk: scalar fallback over the chunk's valid pixels
                int pEnd = chunk * CHUNK_PX + CHUNK_PX;
                if (pEnd > P) pEnd = P;
                for (int p = p0; p < pEnd; p += THREADS) {
                    int cc;
                    if (is64) cc = (int)((const long long*)seg)[(size_t)row * P + p];
                    else      cc = ((const int*)seg)[(size_t)row * P + p];
                    acc += focal_term(__ldg(base + (size_t)cc * P + p));
                }
            }
        }
    }

    // ---- block reduction (8 warps) ----
    for (int off = 16; off > 0; off >>= 1)
        acc += __shfl_down_sync(0xffffffffu, acc, off);
    __shared__ double s_part[8];
    const int lane = tid & 31, wid = tid >> 5;
    if (lane == 0) s_part[wid] = (double)acc;
    __syncthreads();

    __shared__ int s_islast;
    if (tid == 0) {
        double v = 0.0;
        #pragma unroll
        for (int w = 0; w < 8; ++w) v += s_part[w];
        if (v != 0.0) atomicAdd(&g_total, v);
        __threadfence();
        unsigned old = atomicInc(&g_done, gridDim.x - 1u);
        s_islast = (old == gridDim.x - 1u) ? 1 : 0;
    }
    __syncthreads();

    // ---- last block: finalize ----
    if (s_islast) {
        __shared__ float s_loss;
        if (tid == 0) {
            double tot = *((volatile double*)&g_total);
            double cd  = (cnt > 0) ? (double)cnt : 1.0;
            s_loss = (float)(-tot / cd);
            g_total = 0.0;          // reset for next graph replay
            __threadfence();
        }
        __syncthreads();
        float loss = s_loss;
        for (int i = tid; i < out_size; i += blockDim.x)
            out[i] = (i == 0 || i == 2) ? loss : 0.0f;
    }
}

extern "C" void kernel_launch(void* const* d_in, const int* in_sizes, int n_in,
                              void* d_out, int out_size)
{
    const float* logits = (const float*)d_in[0];
    const void*  seg    = d_in[1];
    const void*  label  = d_in[2];

    int N = in_sizes[2];                 // B*S
    int P = in_sizes[1] / N;             // H*W
    int K = in_sizes[0] / in_sizes[1];   // classes

    int chunksPerRow = (P + CHUNK_PX - 1) / CHUNK_PX;
    unsigned int blocks = (unsigned int)N * (unsigned int)chunksPerRow;

    semiloss_fused<<<blocks, THREADS>>>(logits, seg, label,
                                        N, K, P, chunksPerRow,
                                        (float*)d_out, out_size);
}

// round 17
// speedup vs baseline: 1.5950x; 1.0125x over previous
#include <cuda_runtime.h>
#include <cuda_bf16.h>

// SemiLoss focal loss (gamma=6), single fused kernel — R11 config (measured
// best, 10.30/10.40us across two runs) with one micro-optimization: in the
// int64 seg path, load ONLY the low 32-bit word of each class index
// (LDG.32 at byte-stride 8) instead of the full 64-bit value. Same DRAM
// sectors touched, half the seg register pairs / L1 bytes, fewer truncation
// ops in front of the dependent gathers. Validity guaranteed by the dtype
// sniff (odd words verified zero).
//
//   logits : [N, K, P] f32
//   seg    : [N, P]    int64 or int32 (runtime-sniffed)
//   label  : [N]       same int dtype
//   loss = -sum_{n: label[n]!=0} sum_p (1-exp(lp))^6 * lp / count(label!=0)
//   out  = [loss, 0, loss, 0, ...]
//
// Completion: atomicAdd(g_total) + threadfence + atomicInc(g_done) wrapping
// at gridDim.x (self-resetting); last block finalizes out and resets g_total
// so the kernel is deterministic across CUDA-graph replays.

#define THREADS   256
#define PXPT      8                    // pixels per thread
#define CHUNK_PX  (THREADS * PXPT)     // 2048
#define MAXROWS   256                  // N <= 256 (ballot mapper)

__device__ double       g_total = 0.0;
__device__ unsigned int g_done  = 0u;

__device__ __forceinline__ float focal_term(float lp)
{
    float pt = __expf(lp);
    float u  = 1.0f - pt;
    float u2 = u * u;
    return u2 * u2 * u2 * lp;   // positive form; negated at the end
}

__global__ __launch_bounds__(THREADS)
void semiloss_fused(const float* __restrict__ logits,
                    const void*  __restrict__ seg,
                    const void*  __restrict__ label,
                    int N, int K, int P, int chunksPerRow,
                    float* __restrict__ out, int out_size)
{
    const int tid = threadIdx.x;

    // ---- prologue: dtype sniff + active-row ballot map ----
    __shared__ int      s_is64;
    __shared__ unsigned s_masks[MAXROWS / 32];
    __shared__ short    s_rowOf[MAXROWS];   // ordinal -> row
    const int nwords = (N + 31) >> 5;

    if (tid < 32) {
        // int64 (LE) => every odd 32-bit word of seg is 0
        const int* w = (const int*)seg;
        unsigned b = __ballot_sync(0xffffffffu, w[2 * tid + 1] == 0);
        if (tid == 0) s_is64 = (b == 0xffffffffu) ? 1 : 0;
    }
    __syncthreads();
    const int is64 = s_is64;

    {
        bool a = false;
        if (tid < N) {
            long long lv;
            if (is64) lv = ((const long long*)label)[tid];
            else      lv = (long long)((const int*)label)[tid];
            a = (lv != 0);
        }
        unsigned b = __ballot_sync(0xffffffffu, a);
        if ((tid & 31) == 0 && (tid >> 5) < nwords)
            s_masks[tid >> 5] = b;
    }
    __syncthreads();

    int cnt = 0;
    #pragma unroll 4
    for (int j = 0; j < nwords; ++j) cnt += __popc(s_masks[j]);

    if (tid < N) {
        int w = tid >> 5, l = tid & 31;
        if ((s_masks[w] >> l) & 1u) {
            int pre = __popc(s_masks[w] & ((1u << l) - 1u));
            for (int j = 0; j < w; ++j) pre += __popc(s_masks[j]);
            s_rowOf[pre] = (short)tid;
        }
    }
    __syncthreads();

    // ---- gather-reduce over this block's chunk (if any) ----
    float acc = 0.0f;
    {
        const int q = blockIdx.x / chunksPerRow;     // active-row ordinal
        if (q < cnt) {
            const int chunk = blockIdx.x - q * chunksPerRow;
            const int row   = s_rowOf[q];
            const int p0    = chunk * CHUNK_PX + tid;
            const float* base = logits + (size_t)row * (size_t)K * (size_t)P;

            if (p0 + (PXPT - 1) * THREADS < P) {
                int c[PXPT];
                if (is64) {
                    // low 32-bit word only (odd words verified zero by sniff)
                    const int* s = (const int*)seg;
                    const size_t b2 = 2 * ((size_t)row * P + p0);
                    #pragma unroll
                    for (int i = 0; i < PXPT; ++i)
                        c[i] = __ldg(s + b2 + 2 * (size_t)(THREADS * i));
                } else {
                    const int* s = (const int*)seg + (size_t)row * P;
                    #pragma unroll
                    for (int i = 0; i < PXPT; ++i)
                        c[i] = __ldg(s + p0 + THREADS * i);
                }
                float l[PXPT];
                #pragma unroll
                for (int i = 0; i < PXPT; ++i)
                    l[i] = __ldg(base + (size_t)c[i] * P + p0 + THREADS * i);
                #pragma unroll
                for (int i = 0; i < PXPT; ++i)
                    acc += focal_term(l[i]);
            } else {
                // tail chunk: scalar fallback over the chunk's valid pixels
                int pEnd = chunk * CHUNK_PX + CHUNK_PX;
                if (pEnd > P) pEnd = P;
                for (int p = p0; p < pEnd; p += THREADS) {
                    int cc;
                    if (is64) cc = ((const int*)seg)[2 * ((size_t)row * P + p)];
                    else      cc = ((const int*)seg)[(size_t)row * P + p];
                    acc += focal_term(__ldg(base + (size_t)cc * P + p));
                }
            }
        }
    }

    // ---- block reduction (8 warps) ----
    for (int off = 16; off > 0; off >>= 1)
        acc += __shfl_down_sync(0xffffffffu, acc, off);
    __shared__ double s_part[8];
    const int lane = tid & 31, wid = tid >> 5;
    if (lane == 0) s_part[wid] = (double)acc;
    __syncthreads();

    __shared__ int s_islast;
    if (tid == 0) {
        double v = 0.0;
        #pragma unroll
        for (int w = 0; w < 8; ++w) v += s_part[w];
        if (v != 0.0) atomicAdd(&g_total, v);
        __threadfence();
        unsigned old = atomicInc(&g_done, gridDim.x - 1u);
        s_islast = (old == gridDim.x - 1u) ? 1 : 0;
    }
    __syncthreads();

    // ---- last block: finalize ----
    if (s_islast) {
        __shared__ float s_loss;
        if (tid == 0) {
            double tot = *((volatile double*)&g_total);
            double cd  = (cnt > 0) ? (double)cnt : 1.0;
            s_loss = (float)(-tot / cd);
            g_total = 0.0;          // reset for next graph replay
            __threadfence();
        }
        __syncthreads();
        float loss = s_loss;
        for (int i = tid; i < out_size; i += blockDim.x)
            out[i] = (i == 0 || i == 2) ? loss : 0.0f;
    }
}

extern "C" void kernel_launch(void* const* d_in, const int* in_sizes, int n_in,
                              void* d_out, int out_size)
{
    const float* logits = (const float*)d_in[0];
    const void*  seg    = d_in[1];
    const void*  label  = d_in[2];

    int N = in_sizes[2];                 // B*S
    int P = in_sizes[1] / N;             // H*W
    int K = in_sizes[0] / in_sizes[1];   // classes

    int chunksPerRow = (P + CHUNK_PX - 1) / CHUNK_PX;
    unsigned int blocks = (unsigned int)N * (unsigned int)chunksPerRow;

    semiloss_fused<<<blocks, THREADS>>>(logits, seg, label,
                                        N, K, P, chunksPerRow,
                                        (float*)d_out, out_size);
}